// round 2
// baseline (speedup 1.0000x reference)
#include <cuda_runtime.h>
#include <cuda_bf16.h>
#include <stdint.h>

// ============================================================
// Problem dims
// ============================================================
#define IN_F  4096
#define OUT_F 4096
#define BATCH 8192

// GEMM tiling (sm_103 baseline path: cp.async + mma.sync tf32)
#define BM 256
#define BN 128
#define BK 32
#define NK (IN_F / BK)          // 128 k-tiles
#define NPM (BATCH / BM)        // 32
#define NPN (OUT_F / BN)        // 32
#define TILE_GROUP 8
#define THREADS 512
#define STAGES 3

// Padded smem row stride: BK + 4 floats -> conflict-free frag loads
#define SROW (BK + 4)                       // 36 floats = 144 B
#define SM_A_FLOATS (BM * SROW)             // 9216 floats = 36864 B
#define SM_B_FLOATS (BN * SROW)             // 4608 floats = 18432 B
#define STAGE_FLOATS (SM_A_FLOATS + SM_B_FLOATS)
#define SMEM_TOTAL (STAGES * STAGE_FLOATS * 4)   // 165888 B

// ============================================================
// Scratch (static device globals -- no cudaMalloc allowed)
// ============================================================
__device__ float g_W[(size_t)OUT_F * IN_F];   // tf32-rounded materialized weight
__device__ float g_X[(size_t)BATCH * IN_F];   // tf32-rounded x
__device__ float g_bias[OUT_F];

// ============================================================
// Helpers
// ============================================================
__device__ __forceinline__ float rnd_tf32(float f) {
    float r;
    asm("cvt.rna.tf32.f32 %0, %1;" : "=f"(r) : "f"(f));
    return r;
}

__device__ __forceinline__ uint32_t smem_u32(const void* p) {
    uint32_t a;
    asm("{ .reg .u64 t; cvta.to.shared.u64 t, %1; cvt.u32.u64 %0, t; }"
        : "=r"(a) : "l"(p));
    return a;
}

__device__ __forceinline__ void cp16(uint32_t saddr, const void* gptr) {
    asm volatile("cp.async.cg.shared.global [%0], [%1], 16;\n"
                 :: "r"(saddr), "l"(gptr));
}
__device__ __forceinline__ void cp_commit() {
    asm volatile("cp.async.commit_group;\n" ::: "memory");
}
template <int N>
__device__ __forceinline__ void cp_wait() {
    asm volatile("cp.async.wait_group %0;\n" :: "n"(N) : "memory");
}

// m16n8k8 tf32 mma, fp32 accumulate
__device__ __forceinline__ void mma_tf32(float& c0, float& c1, float& c2, float& c3,
                                         uint32_t a0, uint32_t a1, uint32_t a2, uint32_t a3,
                                         uint32_t b0, uint32_t b1) {
    asm volatile(
        "mma.sync.aligned.m16n8k8.row.col.f32.tf32.tf32.f32 "
        "{%0,%1,%2,%3}, {%4,%5,%6,%7}, {%8,%9}, {%0,%1,%2,%3};"
        : "+f"(c0), "+f"(c1), "+f"(c2), "+f"(c3)
        : "r"(a0), "r"(a1), "r"(a2), "r"(a3), "r"(b0), "r"(b1));
}

// ============================================================
// Prep kernels: materialize + tf32 round
// ============================================================
__global__ void prep_w_kernel(const float4* __restrict__ mu,
                              const float4* __restrict__ lv,
                              const float4* __restrict__ eps) {
    size_t i = (size_t)blockIdx.x * blockDim.x + threadIdx.x;   // 4194304 float4s
    float4 m = mu[i], l = lv[i], e = eps[i];
    float4 w;
    w.x = rnd_tf32(m.x + e.x * __expf(0.5f * l.x));
    w.y = rnd_tf32(m.y + e.y * __expf(0.5f * l.y));
    w.z = rnd_tf32(m.z + e.z * __expf(0.5f * l.z));
    w.w = rnd_tf32(m.w + e.w * __expf(0.5f * l.w));
    reinterpret_cast<float4*>(g_W)[i] = w;
}

__global__ void prep_x_kernel(const float4* __restrict__ x) {
    size_t i = (size_t)blockIdx.x * blockDim.x + threadIdx.x;   // 8388608 float4s
    float4 v = x[i];
    float4 w;
    w.x = rnd_tf32(v.x);
    w.y = rnd_tf32(v.y);
    w.z = rnd_tf32(v.z);
    w.w = rnd_tf32(v.w);
    reinterpret_cast<float4*>(g_X)[i] = w;
}

__global__ void prep_bias_kernel(const float* __restrict__ bmu,
                                 const float* __restrict__ blv,
                                 const float* __restrict__ beps) {
    int i = blockIdx.x * blockDim.x + threadIdx.x;
    if (i < OUT_F) g_bias[i] = bmu[i] + beps[i] * __expf(0.5f * blv[i]);
}

// ============================================================
// GEMM: C[256,128] per CTA, 512 threads (16 warps = 8 x 2)
// warp tile 32 x 64; per warp: mtiles {0,1} (16 rows), ntiles 0..7 (8 cols)
// ============================================================
__global__ void __launch_bounds__(THREADS, 1) gemm_kernel(float* __restrict__ out) {
    extern __shared__ float smem[];
    const uint32_t sb = smem_u32(smem);
    const int tid = threadIdx.x;
    const int wid = tid >> 5;
    const int lane = tid & 31;
    const int wm = wid >> 1;      // 0..7  (M direction, 32 rows each)
    const int wn = wid & 1;       // 0..1  (N direction, 64 cols each)
    const int gq = lane >> 2;     // groupID 0..7
    const int tg = lane & 3;      // thread-in-group 0..3

    // tile rasterization for L2 reuse
    int pid = blockIdx.x;
    int grp = pid / (TILE_GROUP * NPN);
    int pin = pid % (TILE_GROUP * NPN);
    int pm  = grp * TILE_GROUP + (pin % TILE_GROUP);
    int pn  = pin / TILE_GROUP;
    const int m0 = pm * BM;
    const int n0 = pn * BN;

    // ---- stage loader: 6 cp16 per thread per stage ----
    auto load_stage = [&](int s, int kt) {
        const int k0 = kt * BK;
        const uint32_t abase = sb + (uint32_t)(s * STAGE_FLOATS) * 4u;
        const uint32_t bbase = abase + SM_A_FLOATS * 4u;
        // A: 256 rows x 32 cols -> 2048 float4, 512 thr -> 4 each
#pragma unroll
        for (int t = 0; t < 4; ++t) {
            int idx = tid + t * THREADS;
            int r = idx >> 3, c4 = idx & 7;
            cp16(abase + (uint32_t)(r * SROW + c4 * 4) * 4u,
                 g_X + (size_t)(m0 + r) * IN_F + k0 + c4 * 4);
        }
        // B: 128 rows x 32 cols -> 1024 float4, 512 thr -> 2 each
#pragma unroll
        for (int t = 0; t < 2; ++t) {
            int idx = tid + t * THREADS;
            int r = idx >> 3, c4 = idx & 7;
            cp16(bbase + (uint32_t)(r * SROW + c4 * 4) * 4u,
                 g_W + (size_t)(n0 + r) * IN_F + k0 + c4 * 4);
        }
    };

    // prologue: stages 0,1
    load_stage(0, 0); cp_commit();
    load_stage(1, 1); cp_commit();

    float c[2][8][4];
#pragma unroll
    for (int mt = 0; mt < 2; ++mt)
#pragma unroll
        for (int nt = 0; nt < 8; ++nt)
#pragma unroll
            for (int j = 0; j < 4; ++j) c[mt][nt][j] = 0.0f;

    // base smem float-offsets for this thread's fragments
    const int a_off0 = (wm * 32 + gq) * SROW + tg;          // row, col base
    const int b_off0 = (wn * 64 + gq) * SROW + tg;

    for (int kt = 0; kt < NK; ++kt) {
        cp_wait<1>();
        __syncthreads();

        // prefetch stage kt+2 into buffer (kt+2)%STAGES (freed by the sync)
        if (kt + 2 < NK) load_stage((kt + 2) % STAGES, kt + 2);
        cp_commit();   // unconditional: keeps group accounting uniform

        const float* sA = smem + (size_t)((kt % STAGES) * STAGE_FLOATS);
        const float* sB = sA + SM_A_FLOATS;

#pragma unroll
        for (int kk = 0; kk < 4; ++kk) {                    // 4 x k8 per BK=32
            const int ko = kk * 8;
            uint32_t a[2][4];
#pragma unroll
            for (int mt = 0; mt < 2; ++mt) {
                const float* p = sA + a_off0 + mt * (16 * SROW) + ko;
                a[mt][0] = __float_as_uint(p[0]);           // (g,   t)
                a[mt][1] = __float_as_uint(p[8 * SROW]);    // (g+8, t)
                a[mt][2] = __float_as_uint(p[4]);           // (g,   t+4)
                a[mt][3] = __float_as_uint(p[8 * SROW + 4]);// (g+8, t+4)
            }
#pragma unroll
            for (int nt = 0; nt < 8; ++nt) {
                const float* p = sB + b_off0 + nt * (8 * SROW) + ko;
                uint32_t b0 = __float_as_uint(p[0]);        // (k=t,   n=g)
                uint32_t b1 = __float_as_uint(p[4]);        // (k=t+4, n=g)
                mma_tf32(c[0][nt][0], c[0][nt][1], c[0][nt][2], c[0][nt][3],
                         a[0][0], a[0][1], a[0][2], a[0][3], b0, b1);
                mma_tf32(c[1][nt][0], c[1][nt][1], c[1][nt][2], c[1][nt][3],
                         a[1][0], a[1][1], a[1][2], a[1][3], b0, b1);
            }
        }
        __syncthreads();
    }

    // ---- epilogue: bias + store (STG.64) ----
#pragma unroll
    for (int mt = 0; mt < 2; ++mt) {
        const int row0 = m0 + wm * 32 + mt * 16 + gq;
#pragma unroll
        for (int nt = 0; nt < 8; ++nt) {
            const int col = n0 + wn * 64 + nt * 8 + 2 * tg;
            const float2 bv = *reinterpret_cast<const float2*>(g_bias + col);
            float2 v0, v1;
            v0.x = c[mt][nt][0] + bv.x;
            v0.y = c[mt][nt][1] + bv.y;
            v1.x = c[mt][nt][2] + bv.x;
            v1.y = c[mt][nt][3] + bv.y;
            *reinterpret_cast<float2*>(out + (size_t)row0 * OUT_F + col) = v0;
            *reinterpret_cast<float2*>(out + (size_t)(row0 + 8) * OUT_F + col) = v1;
        }
    }
}

// ============================================================
// Launch
// ============================================================
extern "C" void kernel_launch(void* const* d_in, const int* in_sizes, int n_in,
                              void* d_out, int out_size) {
    const float* x    = (const float*)d_in[0];
    const float* wmu  = (const float*)d_in[1];
    const float* wlv  = (const float*)d_in[2];
    const float* bmu  = (const float*)d_in[3];
    const float* blv  = (const float*)d_in[4];
    const float* weps = (const float*)d_in[5];
    const float* beps = (const float*)d_in[6];
    float* out = (float*)d_out;

    prep_w_kernel<<<16384, 256>>>((const float4*)wmu, (const float4*)wlv,
                                  (const float4*)weps);
    prep_x_kernel<<<32768, 256>>>((const float4*)x);
    prep_bias_kernel<<<16, 256>>>(bmu, blv, beps);

    cudaFuncSetAttribute(gemm_kernel,
                         cudaFuncAttributeMaxDynamicSharedMemorySize, SMEM_TOTAL);
    gemm_kernel<<<NPM * NPN, THREADS, SMEM_TOTAL>>>(out);
}

// round 3
// speedup vs baseline: 1.8486x; 1.8486x over previous
#include <cuda_runtime.h>
#include <cuda_bf16.h>
#include <stdint.h>

// ============================================================
// Problem dims
// ============================================================
#define IN_F  4096
#define OUT_F 4096
#define BATCH 8192

#define BM 256
#define BN 128
#define BK 32
#define NK (IN_F / BK)          // 128 k-tiles
#define NPM (BATCH / BM)        // 32
#define NPN (OUT_F / BN)        // 32
#define TILE_GROUP 8
#define THREADS 512
#define STAGES 4

#define NK8  (IN_F / 8)         // 512 k8 groups per row
#define NK16 (IN_F / 16)        // 256 k16 groups per row

// SMEM stage layout (packed fragment order, no padding):
//  A: 16 row16-groups x 4 k8 x 32 lanes x float4 = 32768 B
//  B: 16 col8-groups  x 2 k16 x 32 lanes x float4 = 16384 B
#define SM_A_BYTES 32768
#define SM_B_BYTES 16384
#define STAGE_BYTES (SM_A_BYTES + SM_B_BYTES)        // 49152
#define SMEM_TOTAL (STAGES * STAGE_BYTES)            // 196608

// ============================================================
// Scratch (static device globals -- no cudaMalloc allowed)
// g_XP: fragment-packed X:  [row16][k8][lane] float4
// g_WP: fragment-packed W:  [col8][k16][lane] float4
// ============================================================
__device__ float4 g_XP[(size_t)(BATCH / 16) * NK8 * 32];
__device__ float4 g_WP[(size_t)(OUT_F / 8) * NK16 * 32];
__device__ float  g_bias[OUT_F];

// ============================================================
// Helpers
// ============================================================
__device__ __forceinline__ float rnd_tf32(float f) {
    float r;
    asm("cvt.rna.tf32.f32 %0, %1;" : "=f"(r) : "f"(f));
    return r;
}

__device__ __forceinline__ uint32_t smem_u32(const void* p) {
    uint32_t a;
    asm("{ .reg .u64 t; cvta.to.shared.u64 t, %1; cvt.u32.u64 %0, t; }"
        : "=r"(a) : "l"(p));
    return a;
}

__device__ __forceinline__ void cp16(uint32_t saddr, const void* gptr) {
    asm volatile("cp.async.cg.shared.global [%0], [%1], 16;\n"
                 :: "r"(saddr), "l"(gptr));
}
__device__ __forceinline__ void cp_commit() {
    asm volatile("cp.async.commit_group;\n" ::: "memory");
}
template <int N>
__device__ __forceinline__ void cp_wait() {
    asm volatile("cp.async.wait_group %0;\n" :: "n"(N) : "memory");
}

// m16n8k8 tf32 mma, fp32 accumulate
__device__ __forceinline__ void mma_tf32(float& c0, float& c1, float& c2, float& c3,
                                         uint32_t a0, uint32_t a1, uint32_t a2, uint32_t a3,
                                         uint32_t b0, uint32_t b1) {
    asm volatile(
        "mma.sync.aligned.m16n8k8.row.col.f32.tf32.tf32.f32 "
        "{%0,%1,%2,%3}, {%4,%5,%6,%7}, {%8,%9}, {%0,%1,%2,%3};"
        : "+f"(c0), "+f"(c1), "+f"(c2), "+f"(c3)
        : "r"(a0), "r"(a1), "r"(a2), "r"(a3), "r"(b0), "r"(b1));
}

// ============================================================
// Prep: materialize + tf32-round + pack into fragment order
// ============================================================
// A fragment (m16n8k8 row-major A): lane = g*4 + t (g=0..7, t=0..3)
//   a0=(row g, k t) a1=(g+8, t) a2=(g, t+4) a3=(g+8, t+4)
__global__ void prep_x_pack(const float* __restrict__ x) {
    size_t i = (size_t)blockIdx.x * blockDim.x + threadIdx.x;  // 8388608
    int row16 = (int)(i >> 14);          // / (NK8*32 / 16)  -> 512*32=16384
    int rem   = (int)(i & 16383);
    int k8    = rem >> 5;
    int lane  = rem & 31;
    int g = lane >> 2, t = lane & 3;
    const float* p0 = x + (size_t)(row16 * 16 + g) * IN_F + k8 * 8 + t;
    float4 v;
    v.x = rnd_tf32(p0[0]);
    v.y = rnd_tf32(p0[8 * IN_F]);
    v.z = rnd_tf32(p0[4]);
    v.w = rnd_tf32(p0[8 * IN_F + 4]);
    g_XP[i] = v;
}

// B fragment (col-major B): lane's n = g, k values t / t+4; two k8 steps packed:
//   j0=(n g, k16*16+t) j1=(+4) j2=(+8+t) j3=(+12+t)
__global__ void prep_w_pack(const float* __restrict__ mu,
                            const float* __restrict__ lv,
                            const float* __restrict__ eps) {
    size_t i = (size_t)blockIdx.x * blockDim.x + threadIdx.x;  // 4194304
    int col8 = (int)(i >> 13);           // NK16*32 = 8192
    int rem  = (int)(i & 8191);
    int k16  = rem >> 5;
    int lane = rem & 31;
    int g = lane >> 2, t = lane & 3;
    size_t base = (size_t)(col8 * 8 + g) * IN_F + k16 * 16 + t;
    float4 v;
#pragma unroll
    for (int j = 0; j < 4; ++j) {
        size_t a = base + (j & 1) * 4 + (j >> 1) * 8;
        float w = mu[a] + eps[a] * __expf(0.5f * lv[a]);
        (&v.x)[j] = rnd_tf32(w);
    }
    g_WP[i] = v;
}

__global__ void prep_bias_kernel(const float* __restrict__ bmu,
                                 const float* __restrict__ blv,
                                 const float* __restrict__ beps) {
    int i = blockIdx.x * blockDim.x + threadIdx.x;
    if (i < OUT_F) g_bias[i] = bmu[i] + beps[i] * __expf(0.5f * blv[i]);
}

// ============================================================
// GEMM: C[256,128] per CTA, 512 threads (16 warps = 8 x 2)
// warp tile 32 x 64: wm in 0..7 (rows), wn in 0..1 (cols)
// ============================================================
__global__ void __launch_bounds__(THREADS, 1) gemm_kernel(float* __restrict__ out) {
    extern __shared__ char smem[];
    const uint32_t sb = smem_u32(smem);
    const int tid = threadIdx.x;
    const int wid = tid >> 5;
    const int lane = tid & 31;
    const int wm = wid >> 1;      // 0..7
    const int wn = wid & 1;       // 0..1
    const int gq = lane >> 2;
    const int tg = lane & 3;

    int pid = blockIdx.x;
    int grp = pid / (TILE_GROUP * NPN);
    int pin = pid % (TILE_GROUP * NPN);
    int pm  = grp * TILE_GROUP + (pin % TILE_GROUP);
    int pn  = pin / TILE_GROUP;
    const int m0 = pm * BM;
    const int n0 = pn * BN;
    const int m016 = m0 >> 4;     // row16 base
    const int n08  = n0 >> 3;     // col8 base

    // ---- stage loader: 6 cp16/thread; all chunks coalesced ----
    auto load_stage = [&](int s, int kt) {
        const uint32_t abase = sb + (uint32_t)s * STAGE_BYTES;
        const uint32_t bbase = abase + SM_A_BYTES;
        const int kt4 = kt * 4;   // k8 base
        const int kt2 = kt * 2;   // k16 base
#pragma unroll
        for (int t = 0; t < 4; ++t) {            // A: 2048 chunks
            int ca = tid + t * THREADS;
            int r16l = ca >> 7;                  // 128 chunks per row16 group
            int inner = ca & 127;                // k8l*32 + lane
            size_t gidx = ((size_t)(m016 + r16l) * NK8 + kt4 + (inner >> 5)) * 32
                          + (inner & 31);
            cp16(abase + (uint32_t)ca * 16u, g_XP + gidx);
        }
#pragma unroll
        for (int t = 0; t < 2; ++t) {            // B: 1024 chunks
            int cb = tid + t * THREADS;
            int c8l = cb >> 6;                   // 64 chunks per col8 group
            int inner = cb & 63;                 // k16l*32 + lane
            size_t gidx = ((size_t)(n08 + c8l) * NK16 + kt2 + (inner >> 5)) * 32
                          + (inner & 31);
            cp16(bbase + (uint32_t)cb * 16u, g_WP + gidx);
        }
    };

    // prologue: fill 3 stages
    load_stage(0, 0); cp_commit();
    load_stage(1, 1); cp_commit();
    load_stage(2, 2); cp_commit();

    float c[2][8][4];
#pragma unroll
    for (int mt = 0; mt < 2; ++mt)
#pragma unroll
        for (int nt = 0; nt < 8; ++nt)
#pragma unroll
            for (int j = 0; j < 4; ++j) c[mt][nt][j] = 0.0f;

    for (int kt = 0; kt < NK; ++kt) {
        cp_wait<2>();
        __syncthreads();

        if (kt + 3 < NK) load_stage((kt + 3) & 3, kt + 3);
        cp_commit();

        const float4* sA = reinterpret_cast<const float4*>(
            smem + (size_t)(kt & 3) * STAGE_BYTES);
        const float4* sB = reinterpret_cast<const float4*>(
            smem + (size_t)(kt & 3) * STAGE_BYTES + SM_A_BYTES);

#pragma unroll
        for (int k16 = 0; k16 < 2; ++k16) {
            float4 bf[8];
#pragma unroll
            for (int nt = 0; nt < 8; ++nt)
                bf[nt] = sB[(((wn * 8 + nt) * 2 + k16) * 32) + lane];
#pragma unroll
            for (int kk2 = 0; kk2 < 2; ++kk2) {
                const int kk = k16 * 2 + kk2;
                float4 a0 = sA[(((wm * 2 + 0) * 4 + kk) * 32) + lane];
                float4 a1 = sA[(((wm * 2 + 1) * 4 + kk) * 32) + lane];
#pragma unroll
                for (int nt = 0; nt < 8; ++nt) {
                    uint32_t b0 = __float_as_uint(kk2 ? bf[nt].z : bf[nt].x);
                    uint32_t b1 = __float_as_uint(kk2 ? bf[nt].w : bf[nt].y);
                    mma_tf32(c[0][nt][0], c[0][nt][1], c[0][nt][2], c[0][nt][3],
                             __float_as_uint(a0.x), __float_as_uint(a0.y),
                             __float_as_uint(a0.z), __float_as_uint(a0.w), b0, b1);
                    mma_tf32(c[1][nt][0], c[1][nt][1], c[1][nt][2], c[1][nt][3],
                             __float_as_uint(a1.x), __float_as_uint(a1.y),
                             __float_as_uint(a1.z), __float_as_uint(a1.w), b0, b1);
                }
            }
        }
    }

    // ---- epilogue: bias + store ----
#pragma unroll
    for (int mt = 0; mt < 2; ++mt) {
        const int row0 = m0 + wm * 32 + mt * 16 + gq;
#pragma unroll
        for (int nt = 0; nt < 8; ++nt) {
            const int col = n0 + wn * 64 + nt * 8 + 2 * tg;
            const float2 bv = *reinterpret_cast<const float2*>(g_bias + col);
            float2 v0, v1;
            v0.x = c[mt][nt][0] + bv.x;
            v0.y = c[mt][nt][1] + bv.y;
            v1.x = c[mt][nt][2] + bv.x;
            v1.y = c[mt][nt][3] + bv.y;
            *reinterpret_cast<float2*>(out + (size_t)row0 * OUT_F + col) = v0;
            *reinterpret_cast<float2*>(out + (size_t)(row0 + 8) * OUT_F + col) = v1;
        }
    }
}

// ============================================================
// Launch
// ============================================================
extern "C" void kernel_launch(void* const* d_in, const int* in_sizes, int n_in,
                              void* d_out, int out_size) {
    const float* x    = (const float*)d_in[0];
    const float* wmu  = (const float*)d_in[1];
    const float* wlv  = (const float*)d_in[2];
    const float* bmu  = (const float*)d_in[3];
    const float* blv  = (const float*)d_in[4];
    const float* weps = (const float*)d_in[5];
    const float* beps = (const float*)d_in[6];
    float* out = (float*)d_out;

    prep_x_pack<<<32768, 256>>>(x);
    prep_w_pack<<<16384, 256>>>(wmu, wlv, weps);
    prep_bias_kernel<<<16, 256>>>(bmu, blv, beps);

    cudaFuncSetAttribute(gemm_kernel,
                         cudaFuncAttributeMaxDynamicSharedMemorySize, SMEM_TOTAL);
    gemm_kernel<<<NPM * NPN, THREADS, SMEM_TOTAL>>>(out);
}

// round 4
// speedup vs baseline: 1.9742x; 1.0680x over previous
#include <cuda_runtime.h>
#include <cuda_bf16.h>
#include <stdint.h>

// ============================================================
// Problem dims
// ============================================================
#define IN_F  4096
#define OUT_F 4096
#define BATCH 8192

#define BM 256
#define BN 128
#define BK 32
#define NK (IN_F / BK)          // 128 k-tiles
#define NPM (BATCH / BM)        // 32
#define NPN (OUT_F / BN)        // 32
#define TILE_GROUP 8
#define THREADS 256             // 8 warps: 4 (M) x 2 (N), warp tile 64x64
#define STAGES 4

#define NK8  (IN_F / 8)         // 512 k8 groups per row
#define NK16 (IN_F / 16)        // 256 k16 groups per row

// SMEM stage layout (packed fragment order, no padding):
//  A: 16 row16-groups x 4 k8 x 32 lanes x float4 = 32768 B
//  B: 16 col8-groups  x 2 k16 x 32 lanes x float4 = 16384 B
#define SM_A_BYTES 32768
#define SM_B_BYTES 16384
#define STAGE_BYTES (SM_A_BYTES + SM_B_BYTES)        // 49152
#define SMEM_TOTAL (STAGES * STAGE_BYTES)            // 196608

// ============================================================
// Scratch
// ============================================================
__device__ float4 g_XP[(size_t)(BATCH / 16) * NK8 * 32];
__device__ float4 g_WP[(size_t)(OUT_F / 8) * NK16 * 32];
__device__ float  g_bias[OUT_F];

// ============================================================
// Helpers
// ============================================================
__device__ __forceinline__ float rnd_tf32(float f) {
    float r;
    asm("cvt.rna.tf32.f32 %0, %1;" : "=f"(r) : "f"(f));
    return r;
}

__device__ __forceinline__ uint32_t smem_u32(const void* p) {
    uint32_t a;
    asm("{ .reg .u64 t; cvta.to.shared.u64 t, %1; cvt.u32.u64 %0, t; }"
        : "=r"(a) : "l"(p));
    return a;
}

__device__ __forceinline__ void cp16(uint32_t saddr, const void* gptr) {
    asm volatile("cp.async.cg.shared.global [%0], [%1], 16;\n"
                 :: "r"(saddr), "l"(gptr));
}
__device__ __forceinline__ void cp_commit() {
    asm volatile("cp.async.commit_group;\n" ::: "memory");
}
template <int N>
__device__ __forceinline__ void cp_wait() {
    asm volatile("cp.async.wait_group %0;\n" :: "n"(N) : "memory");
}

__device__ __forceinline__ void mma_tf32(float& c0, float& c1, float& c2, float& c3,
                                         uint32_t a0, uint32_t a1, uint32_t a2, uint32_t a3,
                                         uint32_t b0, uint32_t b1) {
    asm volatile(
        "mma.sync.aligned.m16n8k8.row.col.f32.tf32.tf32.f32 "
        "{%0,%1,%2,%3}, {%4,%5,%6,%7}, {%8,%9}, {%0,%1,%2,%3};"
        : "+f"(c0), "+f"(c1), "+f"(c2), "+f"(c3)
        : "r"(a0), "r"(a1), "r"(a2), "r"(a3), "r"(b0), "r"(b1));
}

// ============================================================
// Prep: materialize + tf32-round + pack into fragment order
// ============================================================
__global__ void prep_x_pack(const float* __restrict__ x) {
    size_t i = (size_t)blockIdx.x * blockDim.x + threadIdx.x;  // 8388608
    int row16 = (int)(i >> 14);
    int rem   = (int)(i & 16383);
    int k8    = rem >> 5;
    int lane  = rem & 31;
    int g = lane >> 2, t = lane & 3;
    const float* p0 = x + (size_t)(row16 * 16 + g) * IN_F + k8 * 8 + t;
    float4 v;
    v.x = rnd_tf32(p0[0]);
    v.y = rnd_tf32(p0[8 * IN_F]);
    v.z = rnd_tf32(p0[4]);
    v.w = rnd_tf32(p0[8 * IN_F + 4]);
    g_XP[i] = v;
}

__global__ void prep_w_pack(const float* __restrict__ mu,
                            const float* __restrict__ lv,
                            const float* __restrict__ eps) {
    size_t i = (size_t)blockIdx.x * blockDim.x + threadIdx.x;  // 4194304
    int col8 = (int)(i >> 13);
    int rem  = (int)(i & 8191);
    int k16  = rem >> 5;
    int lane = rem & 31;
    int g = lane >> 2, t = lane & 3;
    size_t base = (size_t)(col8 * 8 + g) * IN_F + k16 * 16 + t;
    float4 v;
#pragma unroll
    for (int j = 0; j < 4; ++j) {
        size_t a = base + (j & 1) * 4 + (j >> 1) * 8;
        float w = mu[a] + eps[a] * __expf(0.5f * lv[a]);
        (&v.x)[j] = rnd_tf32(w);
    }
    g_WP[i] = v;
}

__global__ void prep_bias_kernel(const float* __restrict__ bmu,
                                 const float* __restrict__ blv,
                                 const float* __restrict__ beps) {
    int i = blockIdx.x * blockDim.x + threadIdx.x;
    if (i < OUT_F) g_bias[i] = bmu[i] + beps[i] * __expf(0.5f * blv[i]);
}

// ============================================================
// GEMM: C[256,128] per CTA, 256 threads (8 warps = 4 x 2)
// warp tile 64 x 64: wm in 0..3 (64 rows), wn in 0..1 (64 cols)
// ============================================================
__global__ void __launch_bounds__(THREADS, 1) gemm_kernel(float* __restrict__ out) {
    extern __shared__ char smem[];
    const uint32_t sb = smem_u32(smem);
    const int tid = threadIdx.x;
    const int wid = tid >> 5;
    const int lane = tid & 31;
    const int wm = wid >> 1;      // 0..3  (M, 64 rows)
    const int wn = wid & 1;       // 0..1  (N, 64 cols)
    const int gq = lane >> 2;
    const int tg = lane & 3;

    int pid = blockIdx.x;
    int grp = pid / (TILE_GROUP * NPN);
    int pin = pid % (TILE_GROUP * NPN);
    int pm  = grp * TILE_GROUP + (pin % TILE_GROUP);
    int pn  = pin / TILE_GROUP;
    const int m0 = pm * BM;
    const int n0 = pn * BN;
    const int m016 = m0 >> 4;
    const int n08  = n0 >> 3;

    // ---- stage loader: 12 cp16/thread ----
    auto load_stage = [&](int s, int kt) {
        const uint32_t abase = sb + (uint32_t)s * STAGE_BYTES;
        const uint32_t bbase = abase + SM_A_BYTES;
        const int kt4 = kt * 4;
        const int kt2 = kt * 2;
#pragma unroll
        for (int t = 0; t < 8; ++t) {            // A: 2048 chunks
            int ca = tid + t * THREADS;
            int r16l = ca >> 7;
            int inner = ca & 127;
            size_t gidx = ((size_t)(m016 + r16l) * NK8 + kt4 + (inner >> 5)) * 32
                          + (inner & 31);
            cp16(abase + (uint32_t)ca * 16u, g_XP + gidx);
        }
#pragma unroll
        for (int t = 0; t < 4; ++t) {            // B: 1024 chunks
            int cb = tid + t * THREADS;
            int c8l = cb >> 6;
            int inner = cb & 63;
            size_t gidx = ((size_t)(n08 + c8l) * NK16 + kt2 + (inner >> 5)) * 32
                          + (inner & 31);
            cp16(bbase + (uint32_t)cb * 16u, g_WP + gidx);
        }
    };

    load_stage(0, 0); cp_commit();
    load_stage(1, 1); cp_commit();
    load_stage(2, 2); cp_commit();

    float c[4][8][4];
#pragma unroll
    for (int mt = 0; mt < 4; ++mt)
#pragma unroll
        for (int nt = 0; nt < 8; ++nt)
#pragma unroll
            for (int j = 0; j < 4; ++j) c[mt][nt][j] = 0.0f;

    for (int kt = 0; kt < NK; ++kt) {
        cp_wait<2>();
        __syncthreads();

        if (kt + 3 < NK) load_stage((kt + 3) & 3, kt + 3);
        cp_commit();

        const float4* sA = reinterpret_cast<const float4*>(
            smem + (size_t)(kt & 3) * STAGE_BYTES);
        const float4* sB = reinterpret_cast<const float4*>(
            smem + (size_t)(kt & 3) * STAGE_BYTES + SM_A_BYTES);

#pragma unroll
        for (int k16 = 0; k16 < 2; ++k16) {
            float4 bf[8];
#pragma unroll
            for (int nt = 0; nt < 8; ++nt)
                bf[nt] = sB[(((wn * 8 + nt) * 2 + k16) * 32) + lane];
#pragma unroll
            for (int kk2 = 0; kk2 < 2; ++kk2) {
                const int kk = k16 * 2 + kk2;
                float4 af[4];
#pragma unroll
                for (int mt = 0; mt < 4; ++mt)
                    af[mt] = sA[(((wm * 4 + mt) * 4 + kk) * 32) + lane];
#pragma unroll
                for (int nt = 0; nt < 8; ++nt) {
                    uint32_t b0 = __float_as_uint(kk2 ? bf[nt].z : bf[nt].x);
                    uint32_t b1 = __float_as_uint(kk2 ? bf[nt].w : bf[nt].y);
#pragma unroll
                    for (int mt = 0; mt < 4; ++mt) {
                        mma_tf32(c[mt][nt][0], c[mt][nt][1], c[mt][nt][2], c[mt][nt][3],
                                 __float_as_uint(af[mt].x), __float_as_uint(af[mt].y),
                                 __float_as_uint(af[mt].z), __float_as_uint(af[mt].w),
                                 b0, b1);
                    }
                }
            }
        }
    }

    // ---- epilogue: bias + store ----
#pragma unroll
    for (int mt = 0; mt < 4; ++mt) {
        const int row0 = m0 + wm * 64 + mt * 16 + gq;
#pragma unroll
        for (int nt = 0; nt < 8; ++nt) {
            const int col = n0 + wn * 64 + nt * 8 + 2 * tg;
            const float2 bv = *reinterpret_cast<const float2*>(g_bias + col);
            float2 v0, v1;
            v0.x = c[mt][nt][0] + bv.x;
            v0.y = c[mt][nt][1] + bv.y;
            v1.x = c[mt][nt][2] + bv.x;
            v1.y = c[mt][nt][3] + bv.y;
            *reinterpret_cast<float2*>(out + (size_t)row0 * OUT_F + col) = v0;
            *reinterpret_cast<float2*>(out + (size_t)(row0 + 8) * OUT_F + col) = v1;
        }
    }
}

// ============================================================
// Launch
// ============================================================
extern "C" void kernel_launch(void* const* d_in, const int* in_sizes, int n_in,
                              void* d_out, int out_size) {
    const float* x    = (const float*)d_in[0];
    const float* wmu  = (const float*)d_in[1];
    const float* wlv  = (const float*)d_in[2];
    const float* bmu  = (const float*)d_in[3];
    const float* blv  = (const float*)d_in[4];
    const float* weps = (const float*)d_in[5];
    const float* beps = (const float*)d_in[6];
    float* out = (float*)d_out;

    prep_x_pack<<<32768, 256>>>(x);
    prep_w_pack<<<16384, 256>>>(wmu, wlv, weps);
    prep_bias_kernel<<<16, 256>>>(bmu, blv, beps);

    cudaFuncSetAttribute(gemm_kernel,
                         cudaFuncAttributeMaxDynamicSharedMemorySize, SMEM_TOTAL);
    gemm_kernel<<<NPM * NPN, THREADS, SMEM_TOTAL>>>(out);
}